// round 5
// baseline (speedup 1.0000x reference)
#include <cuda_runtime.h>
#include <cstdint>
#include <math.h>

#define TSTEPS 20
#define BATCH  128
#define EDIM   512
#define HDIM   512
#define GDIM   2048
#define VOCAB  32000
#define CAPLEN 20

#if defined(__CUDA_ARCH__) && (__CUDA_ARCH__ == 1030) && \
    (defined(__CUDA_ARCH_FEAT_SM103_ALL) || defined(__CUDA_ARCH_SPECIFIC__))
#define HAS_TCGEN05 1
#else
#define HAS_TCGEN05 0
#endif

__device__ __forceinline__ uint32_t smem_to_u32(const void* p) {
    uint32_t a;
    asm("{ .reg .u64 t; cvta.to.shared.u64 t, %1; cvt.u32.u64 %0, t; }" : "=r"(a) : "l"(p));
    return a;
}
__device__ __forceinline__ void tf32split(float x, float& hi, float& lo) {
    uint32_t h; asm("cvt.rna.tf32.f32 %0, %1;" : "=r"(h) : "f"(x));
    hi = __uint_as_float(h);
    float r = x - hi;
    uint32_t l; asm("cvt.rna.tf32.f32 %0, %1;" : "=r"(l) : "f"(r));
    lo = __uint_as_float(l);
}
// SW128 swizzled byte offset, K-major tile with 128B (32-float) rows
__device__ __forceinline__ uint32_t swz32(int r, int kk) {
    uint32_t b = ((uint32_t)(r >> 3) << 10) + ((uint32_t)(r & 7) << 7) + ((uint32_t)kk << 2);
    return b ^ ((b >> 3) & 0x70);
}
#define MBARRIER_INIT(m, c) \
    asm volatile("mbarrier.init.shared.b64 [%0], %1;" :: "r"((uint32_t)(m)), "r"((uint32_t)(c)) : "memory")
#define MBARRIER_WAIT_PARITY(m, par) do { \
    uint32_t _m = (uint32_t)(m), _p = (uint32_t)(par), _d; \
    asm volatile("{\n\t.reg .pred p;\n\t" \
        "mbarrier.try_wait.parity.acquire.cta.shared::cta.b64 p, [%1], %2;\n\t" \
        "selp.b32 %0, 1, 0, p;\n\t}" : "=r"(_d) : "r"(_m), "r"(_p) : "memory"); \
    if (!_d) { \
        asm volatile("{\n\t.reg .pred P1;\n\t" \
            "WL_%=:\n\t" \
            "mbarrier.try_wait.parity.acquire.cta.shared::cta.b64 P1, [%0], %1, 0x989680;\n\t" \
            "@P1 bra.uni WD_%=;\n\tbra.uni WL_%=;\n\tWD_%=:\n\t}" :: "r"(_m), "r"(_p) : "memory"); \
    } \
} while(0)

#if HAS_TCGEN05
__device__ __forceinline__ uint32_t elect_one_pred() {
    uint32_t pr;
    asm volatile("{\n\t.reg .pred p;\n\telect.sync _|p, 0xFFFFFFFF;\n\t"
                 "selp.b32 %0, 1, 0, p;\n\t}" : "=r"(pr));
    return pr;
}
#define TCGEN05_ALLOC(sa, n) \
    asm volatile("tcgen05.alloc.cta_group::1.sync.aligned.shared::cta.b32 [%0], %1;" \
        :: "r"((uint32_t)(sa)), "r"((uint32_t)(n)) : "memory")
#define TCGEN05_DEALLOC(t, n) \
    asm volatile("tcgen05.dealloc.cta_group::1.sync.aligned.b32 %0, %1;" :: "r"(t), "r"((uint32_t)(n)))
#define TCGEN05_RELINQ() asm volatile("tcgen05.relinquish_alloc_permit.cta_group::1.sync.aligned;")
#define TCGEN05_COMMIT(m) \
    asm volatile("tcgen05.commit.cta_group::1.mbarrier::arrive::one.shared::cluster.b64 [%0];" \
        :: "r"((uint32_t)(m)) : "memory")
#define TCGEN05_WAIT_LD() asm volatile("tcgen05.wait::ld.sync.aligned;" ::: "memory")
#define TCGEN05_FENCE_AFTER() asm volatile("tcgen05.fence::after_thread_sync;" ::: "memory")
#define FENCE_ASYNC() asm volatile("fence.proxy.async.shared::cta;" ::: "memory")
#define TCGEN05_LD_X32(r, ta) \
    asm volatile("tcgen05.ld.sync.aligned.32x32b.x32.b32 " \
        "{%0, %1, %2, %3, %4, %5, %6, %7, %8, %9, %10, %11, %12, %13, %14, %15, " \
        " %16, %17, %18, %19, %20, %21, %22, %23, %24, %25, %26, %27, %28, %29, %30, %31}, [%32];" \
        : "=r"((r)[0]), "=r"((r)[1]), "=r"((r)[2]), "=r"((r)[3]), "=r"((r)[4]), "=r"((r)[5]), \
          "=r"((r)[6]), "=r"((r)[7]), "=r"((r)[8]), "=r"((r)[9]), "=r"((r)[10]), "=r"((r)[11]), \
          "=r"((r)[12]), "=r"((r)[13]), "=r"((r)[14]), "=r"((r)[15]), "=r"((r)[16]), "=r"((r)[17]), \
          "=r"((r)[18]), "=r"((r)[19]), "=r"((r)[20]), "=r"((r)[21]), "=r"((r)[22]), "=r"((r)[23]), \
          "=r"((r)[24]), "=r"((r)[25]), "=r"((r)[26]), "=r"((r)[27]), "=r"((r)[28]), "=r"((r)[29]), \
          "=r"((r)[30]), "=r"((r)[31]) : "r"(ta))
#define TCGEN05_MMA_TF32(d, ad, bd, id, en) do { \
    uint32_t _e = (en) ? 1u : 0u; \
    asm volatile("{\n\t.reg .pred p;\n\tsetp.ne.u32 p, %4, 0;\n\t" \
        "tcgen05.mma.cta_group::1.kind::tf32 [%0], %1, %2, %3, {%5, %5, %5, %5}, p;\n\t}" \
        :: "r"(d), "l"(ad), "l"(bd), "r"(id), "r"(_e), "r"(0u) : "memory"); \
} while(0)
static __device__ __forceinline__ uint64_t make_sw128_desc(uint32_t base) {
    uint64_t d = (uint64_t(2) << 61) | (uint64_t(1) << 46) |
                 (uint64_t(64) << 32) | (uint64_t(1) << 16);
    return d | ((uint64_t)(base >> 4) & 0x3FFF);
}
#endif

#define IDESC_N64  ((1u << 4) | (2u << 7) | (2u << 10) | (8u  << 17) | (8u << 24))
#define IDESC_N128 ((1u << 4) | (2u << 7) | (2u << 10) | (16u << 17) | (8u << 24))

// ============ device scratch ============
__device__ float d_xseq [TSTEPS * BATCH * EDIM];
__device__ float d_xw   [TSTEPS * BATCH * GDIM];
__device__ float d_whh_hi[GDIM * HDIM];
__device__ float d_whh_lo[GDIM * HDIM];
__device__ float d_hhi[2 * BATCH * HDIM];
__device__ float d_hlo[2 * BATCH * HDIM];
__device__ float d_cstate[BATCH * HDIM];
__device__ float d_hall[TSTEPS * BATCH * HDIM];
__device__ float d_hc  [TSTEPS * BATCH * HDIM];
__device__ int   d_off [TSTEPS + 1];

// ============ small kernels ============
__global__ void compute_off_kernel(const int* __restrict__ lengths, int* __restrict__ off) {
    __shared__ int sl[BATCH];
    __shared__ int cnt[TSTEPS];
    int tid = threadIdx.x;
    if (tid < BATCH) sl[tid] = lengths[tid];
    __syncthreads();
    if (tid < TSTEPS) {
        int c = 0;
        for (int b = 0; b < BATCH; b++) c += (sl[b] > tid);
        cnt[tid] = c;
    }
    __syncthreads();
    if (tid == 0) {
        int acc = 0;
        for (int t = 0; t < TSTEPS; t++) { off[t] = acc; acc += cnt[t]; }
        off[TSTEPS] = acc;
    }
}

__global__ void build_xseq_kernel(const float* __restrict__ features,
                                  const int* __restrict__ captions,
                                  const float* __restrict__ embed_w,
                                  float* __restrict__ xseq) {
    int gid = blockIdx.x * blockDim.x + threadIdx.x;
    int e4 = gid % (EDIM / 4);
    int row = gid / (EDIM / 4);
    int t = row / BATCH, b = row % BATCH;
    const float4* src;
    if (t == 0) src = (const float4*)(features + (size_t)b * EDIM);
    else {
        int tok = captions[b * CAPLEN + (t - 1)];
        src = (const float4*)(embed_w + (size_t)tok * EDIM);
    }
    ((float4*)xseq)[gid] = src[e4];
}

// permute + tf32-split w_hh: new row np -> orig row (r>>4)*512 + (np>>6)*16 + (r&15)
__global__ void prep_whh_kernel(const float* __restrict__ w_hh,
                                float* __restrict__ whi, float* __restrict__ wlo) {
    int idx = blockIdx.x * 256 + threadIdx.x;   // 2048*128 f4 groups
    int np = idx >> 7;
    int k4 = (idx & 127) << 2;
    int r = np & 63;
    int orig = (r >> 4) * HDIM + (np >> 6) * 16 + (r & 15);
    float4 w = *(const float4*)(w_hh + (size_t)orig * HDIM + k4);
    float4 hi, lo;
    tf32split(w.x, hi.x, lo.x); tf32split(w.y, hi.y, lo.y);
    tf32split(w.z, hi.z, lo.z); tf32split(w.w, hi.w, lo.w);
    *(float4*)(whi + (size_t)np * HDIM + k4) = hi;
    *(float4*)(wlo + (size_t)np * HDIM + k4) = lo;
}

__global__ void split_h0_kernel(const float* __restrict__ h0,
                                float* __restrict__ hhi, float* __restrict__ hlo) {
    int i = (blockIdx.x * 256 + threadIdx.x) * 4;
    float4 v = *(const float4*)(h0 + i);
    float4 hi, lo;
    tf32split(v.x, hi.x, lo.x); tf32split(v.y, hi.y, lo.y);
    tf32split(v.z, hi.z, lo.z); tf32split(v.w, hi.w, lo.w);
    *(float4*)(hhi + i) = hi;
    *(float4*)(hlo + i) = lo;
}

__global__ void gather_h_kernel(const float* __restrict__ hall,
                                const int* __restrict__ off, float* __restrict__ hc) {
    int row = blockIdx.x;
    int t = row / BATCH, b = row % BATCH;
    if (b >= off[t + 1] - off[t]) return;
    const float4* s = (const float4*)(hall + (size_t)row * HDIM);
    float4* d = (float4*)(hc + (size_t)(off[t] + b) * HDIM);
    d[threadIdx.x] = s[threadIdx.x];
}

// ============ fp32 SIMT GEMM for xW ============
template<int BM, int BN, int BK, int TM, int TN>
__global__ void __launch_bounds__((BM / TM) * (BN / TN))
gemm_nt_kernel(const float* __restrict__ A, const float* __restrict__ B,
               const float* __restrict__ bias0, const float* __restrict__ bias1,
               float* __restrict__ C, int M, int N, int K) {
    constexpr int NT = (BM / TM) * (BN / TN);
    __shared__ float As[BK][BM];
    __shared__ float Bs[BK][BN];
    const int tid = threadIdx.x;
    const int m0 = blockIdx.y * BM, n0 = blockIdx.x * BN;
    const int tx = tid % (BN / TN), ty = tid / (BN / TN);
    float acc[TM][TN];
    #pragma unroll
    for (int i = 0; i < TM; i++)
        #pragma unroll
        for (int j = 0; j < TN; j++) acc[i][j] = 0.0f;
    for (int kt = 0; kt < K; kt += BK) {
        #pragma unroll
        for (int it = 0; it < (BM * BK / 4) / NT; it++) {
            int i = tid + it * NT;
            int m = i / (BK / 4), k4 = (i % (BK / 4)) * 4;
            float4 v = *(const float4*)(A + (size_t)(m0 + m) * K + kt + k4);
            As[k4][m] = v.x; As[k4 + 1][m] = v.y; As[k4 + 2][m] = v.z; As[k4 + 3][m] = v.w;
        }
        #pragma unroll
        for (int it = 0; it < (BN * BK / 4) / NT; it++) {
            int i = tid + it * NT;
            int n = i / (BK / 4), k4 = (i % (BK / 4)) * 4;
            float4 v = *(const float4*)(B + (size_t)(n0 + n) * K + kt + k4);
            Bs[k4][n] = v.x; Bs[k4 + 1][n] = v.y; Bs[k4 + 2][n] = v.z; Bs[k4 + 3][n] = v.w;
        }
        __syncthreads();
        #pragma unroll
        for (int k = 0; k < BK; k++) {
            float a[TM], b[TN];
            #pragma unroll
            for (int i = 0; i < TM; i++) a[i] = As[k][ty * TM + i];
            #pragma unroll
            for (int j = 0; j < TN; j++) b[j] = Bs[k][tx * TN + j];
            #pragma unroll
            for (int i = 0; i < TM; i++)
                #pragma unroll
                for (int j = 0; j < TN; j++) acc[i][j] = fmaf(a[i], b[j], acc[i][j]);
        }
        __syncthreads();
    }
    #pragma unroll
    for (int i = 0; i < TM; i++) {
        int gm = m0 + ty * TM + i;
        #pragma unroll
        for (int j = 0; j < TN; j++) {
            int gn = n0 + tx * TN + j;
            C[(size_t)gm * N + gn] = acc[i][j] + bias0[gn] + bias1[gn];
        }
    }
}

// ============ fused recurrent step (3-pass tf32 GEMM + LSTM cell) ============
// grid=32; CTA `tile` computes permuted gate cols [64*tile, 64*tile+64) for all 128 rows
__global__ void __launch_bounds__(256, 1)
step_kernel(const float* __restrict__ xw_t,
            const float* __restrict__ hhi_in, const float* __restrict__ hlo_in,
            const float* __restrict__ whi, const float* __restrict__ wlo,
            float* __restrict__ cstate, float* __restrict__ hall_t,
            float* __restrict__ hhi_out, float* __restrict__ hlo_out) {
    extern __shared__ float dsm[];
    const int tid = threadIdx.x, wid = tid >> 5;
    const int tile = blockIdx.x;
#if HAS_TCGEN05
    __shared__ uint32_t s_tmem[1];
    __shared__ __align__(8) uint64_t s_mbar;
    uint32_t dyn = smem_to_u32(dsm);
    uint32_t base = (dyn + 1023u) & ~1023u;
    char* bp = (char*)dsm + (base - dyn);
    uint32_t mb = smem_to_u32(&s_mbar);
    if (tid == 0) MBARRIER_INIT(mb, 1);
    if (wid == 0) { TCGEN05_ALLOC(smem_to_u32(&s_tmem[0]), 64); TCGEN05_RELINQ(); }
    __syncthreads();
    const uint32_t tmem = s_tmem[0];

    // layout per chunk (K=32): A_hi 16K | A_lo 16K | B_hi 8K | B_lo 8K = 48K
    for (int ch = 0; ch < 16; ch++) {
        const int kt = ch * 32;
        #pragma unroll
        for (int it = 0; it < 4; it++) {          // A: 128 rows x 32 cols
            int i = tid + (it << 8);
            int r = i >> 3, kk = (i & 7) << 2;
            uint32_t o = swz32(r, kk);
            *(float4*)(bp + o)         = *(const float4*)(hhi_in + (size_t)r * HDIM + kt + kk);
            *(float4*)(bp + 16384 + o) = *(const float4*)(hlo_in + (size_t)r * HDIM + kt + kk);
        }
        #pragma unroll
        for (int it = 0; it < 2; it++) {          // B: 64 rows x 32 cols
            int i = tid + (it << 8);
            int r = i >> 3, kk = (i & 7) << 2;
            uint32_t o = swz32(r, kk);
            size_t g = (size_t)(tile * 64 + r) * HDIM + kt + kk;
            *(float4*)(bp + 32768 + o) = *(const float4*)(whi + g);
            *(float4*)(bp + 40960 + o) = *(const float4*)(wlo + g);
        }
        __syncthreads();
        if (wid == 0 && elect_one_pred()) {
            FENCE_ASYNC();
            uint64_t ah = make_sw128_desc(base);
            uint64_t al = make_sw128_desc(base + 16384);
            uint64_t bh = make_sw128_desc(base + 32768);
            uint64_t bl = make_sw128_desc(base + 40960);
            #pragma unroll
            for (int ks = 0; ks < 4; ks++) {
                uint32_t o = ks * 2;
                TCGEN05_MMA_TF32(tmem, ah + o, bh + o, IDESC_N64, !(ch == 0 && ks == 0));
                TCGEN05_MMA_TF32(tmem, ah + o, bl + o, IDESC_N64, 1);
                TCGEN05_MMA_TF32(tmem, al + o, bh + o, IDESC_N64, 1);
            }
            TCGEN05_COMMIT(mb);
        }
        MBARRIER_WAIT_PARITY(mb, ch & 1);
        __syncthreads();
    }
    TCGEN05_FENCE_AFTER();

    if (wid < 4) {
        int m = tid;                               // batch row 0..127
        uint32_t r0[32], r1[32];
        TCGEN05_LD_X32(r0, tmem);                  // cols 0..31: i(16), f(16)
        TCGEN05_LD_X32(r1, tmem + 32);             // cols 32..63: g(16), o(16)
        TCGEN05_WAIT_LD();
        const float* xr = xw_t + (size_t)m * GDIM;
        float* cp = cstate + (size_t)m * HDIM + tile * 16;
        size_t ho = (size_t)m * HDIM + tile * 16;
        #pragma unroll
        for (int j = 0; j < 16; j++) {
            int col = tile * 16 + j;
            float gi = __uint_as_float(r0[j])      + xr[col];
            float gf = __uint_as_float(r0[16 + j]) + xr[HDIM + col];
            float gg = __uint_as_float(r1[j])      + xr[2 * HDIM + col];
            float go = __uint_as_float(r1[16 + j]) + xr[3 * HDIM + col];
            float iv = 1.0f / (1.0f + expf(-gi));
            float fv = 1.0f / (1.0f + expf(-gf));
            float gv = tanhf(gg);
            float ov = 1.0f / (1.0f + expf(-go));
            float cc = fv * cp[j] + iv * gv;
            cp[j] = cc;
            float hh = ov * tanhf(cc);
            hall_t[ho + j] = hh;
            float hi, lo;
            tf32split(hh, hi, lo);
            hhi_out[ho + j] = hi;
            hlo_out[ho + j] = lo;
        }
    }
    __syncthreads();
    if (wid == 0) TCGEN05_DEALLOC(tmem, 64);
#else
    // compile-only fallback (runtime always picks the sm_103a image)
    for (int e = tid; e < BATCH * 16; e += 256) {
        int m = e >> 4, j = e & 15;
        int col = tile * 16 + j;
        float g[4];
        for (int q = 0; q < 4; q++) {
            float acc = xw_t[(size_t)m * GDIM + q * HDIM + col];
            for (int k = 0; k < HDIM; k++)
                acc += (hhi_in[(size_t)m * HDIM + k] + hlo_in[(size_t)m * HDIM + k]) *
                       (whi[(size_t)(tile * 64 + q * 16 + j) * HDIM + k] +
                        wlo[(size_t)(tile * 64 + q * 16 + j) * HDIM + k]);
            g[q] = acc;
        }
        float iv = 1.0f / (1.0f + expf(-g[0]));
        float fv = 1.0f / (1.0f + expf(-g[1]));
        float gv = tanhf(g[2]);
        float ov = 1.0f / (1.0f + expf(-g[3]));
        float cc = fv * cstate[(size_t)m * HDIM + col] + iv * gv;
        cstate[(size_t)m * HDIM + col] = cc;
        float hh = ov * tanhf(cc);
        hall_t[(size_t)m * HDIM + col] = hh;
        float hi, lo;
        tf32split(hh, hi, lo);
        hhi_out[(size_t)m * HDIM + col] = hi;
        hlo_out[(size_t)m * HDIM + col] = lo;
    }
#endif
}

// ============ projection GEMM: tcgen05 tf32 (proven R3) ============
__device__ __forceinline__ uint32_t tile_swz_off(int r, int kk) {
    uint32_t b = (uint32_t)(((r >> 3) + ((kk >> 5) << 4)) << 10)
               + (uint32_t)((r & 7) << 7) + (uint32_t)((kk & 31) << 2);
    return b ^ ((b >> 3) & 0x70);
}

__global__ void __launch_bounds__(256, 1)
proj_tf32_kernel(const float* __restrict__ A, const float* __restrict__ B,
                 const float* __restrict__ bias, float* __restrict__ C,
                 int M, int N, int K) {
    extern __shared__ float dsm[];
    const int tid = threadIdx.x, wid = tid >> 5, lid = tid & 31;
    const int m0 = blockIdx.x * 128, n0 = blockIdx.y * 128;
#if HAS_TCGEN05
    __shared__ uint32_t s_tmem[1];
    __shared__ __align__(8) uint64_t s_mbar;
    __shared__ float s_bias[128];
    uint32_t dyn = smem_to_u32(dsm);
    uint32_t base = (dyn + 1023u) & ~1023u;
    char* bp = (char*)dsm + (base - dyn);
    char* aA = bp;
    char* aB = bp + 32768;
    float* Ds = (float*)bp;
    uint32_t mbar = smem_to_u32(&s_mbar);
    if (tid < 128) s_bias[tid] = bias[n0 + tid];
    if (tid == 0) MBARRIER_INIT(mbar, 1);
    if (wid == 0) { TCGEN05_ALLOC(smem_to_u32(&s_tmem[0]), 128); TCGEN05_RELINQ(); }
    __syncthreads();
    const uint32_t tmem = s_tmem[0];

    for (int ch = 0; ch < K / 64; ch++) {
        const int kt = ch * 64;
        #pragma unroll
        for (int it = 0; it < 8; it++) {
            int i = tid + (it << 8);
            int r = i >> 4, kk = (i & 15) << 2;
            uint32_t off = tile_swz_off(r, kk);
            *(float4*)(aA + off) = *(const float4*)(A + (size_t)(m0 + r) * K + kt + kk);
            *(float4*)(aB + off) = *(const float4*)(B + (size_t)(n0 + r) * K + kt + kk);
        }
        __syncthreads();
        if (wid == 0 && elect_one_pred()) {
            FENCE_ASYNC();
            uint64_t ad = make_sw128_desc(base);
            uint64_t bd = make_sw128_desc(base + 32768);
            const uint32_t ks[8] = {0, 2, 4, 6, 1024, 1026, 1028, 1030};
            #pragma unroll
            for (int s = 0; s < 8; s++)
                TCGEN05_MMA_TF32(tmem, ad + ks[s], bd + ks[s], IDESC_N128, (ch > 0) || (s > 0));
            TCGEN05_COMMIT(mbar);
        }
        MBARRIER_WAIT_PARITY(mbar, ch & 1);
        __syncthreads();
    }
    TCGEN05_FENCE_AFTER();

    if (wid < 4) {
        const int row = (wid << 5) + lid;
        #pragma unroll
        for (int cb = 0; cb < 128; cb += 32) {
            uint32_t r[32];
            TCGEN05_LD_X32(r, tmem + cb);
            TCGEN05_WAIT_LD();
            #pragma unroll
            for (int q = 0; q < 8; q++) {
                float4 v = { __uint_as_float(r[4*q]), __uint_as_float(r[4*q+1]),
                             __uint_as_float(r[4*q+2]), __uint_as_float(r[4*q+3]) };
                *(float4*)&Ds[row * 132 + cb + 4 * q] = v;
            }
        }
    }
    __syncthreads();
    #pragma unroll
    for (int it = 0; it < 16; it++) {
        int i = tid + (it << 8);
        int r = i >> 5, c4 = (i & 31) << 2;
        int gm = m0 + r;
        if (gm < M) {
            float4 v = *(const float4*)&Ds[r * 132 + c4];
            float4 b = *(const float4*)&s_bias[c4];
            v.x += b.x; v.y += b.y; v.z += b.z; v.w += b.w;
            *(float4*)(C + (size_t)gm * N + n0 + c4) = v;
        }
    }
    __syncthreads();
    if (wid == 0) TCGEN05_DEALLOC(tmem, 128);
#else
    float* As = dsm;
    float* Bs = dsm + 16 * 128;
    const int tx = tid % 16, ty = tid / 16;
    float acc[8][8];
    #pragma unroll
    for (int i = 0; i < 8; i++)
        #pragma unroll
        for (int j = 0; j < 8; j++) acc[i][j] = 0.0f;
    for (int kt = 0; kt < K; kt += 16) {
        #pragma unroll
        for (int it = 0; it < 2; it++) {
            int i = tid + it * 256;
            int m = i / 4, k4 = (i % 4) * 4;
            float4 va = *(const float4*)(A + (size_t)(m0 + m) * K + kt + k4);
            As[k4 * 128 + m] = va.x; As[(k4+1)*128+m] = va.y; As[(k4+2)*128+m] = va.z; As[(k4+3)*128+m] = va.w;
            float4 vb = *(const float4*)(B + (size_t)(n0 + m) * K + kt + k4);
            Bs[k4 * 128 + m] = vb.x; Bs[(k4+1)*128+m] = vb.y; Bs[(k4+2)*128+m] = vb.z; Bs[(k4+3)*128+m] = vb.w;
        }
        __syncthreads();
        #pragma unroll
        for (int k = 0; k < 16; k++) {
            float a[8], b[8];
            #pragma unroll
            for (int i = 0; i < 8; i++) a[i] = As[k * 128 + ty * 8 + i];
            #pragma unroll
            for (int j = 0; j < 8; j++) b[j] = Bs[k * 128 + tx * 8 + j];
            #pragma unroll
            for (int i = 0; i < 8; i++)
                #pragma unroll
                for (int j = 0; j < 8; j++) acc[i][j] = fmaf(a[i], b[j], acc[i][j]);
        }
        __syncthreads();
    }
    #pragma unroll
    for (int i = 0; i < 8; i++) {
        int gm = m0 + ty * 8 + i;
        if (gm >= M) continue;
        #pragma unroll
        for (int j = 0; j < 8; j++) {
            int gn = n0 + tx * 8 + j;
            C[(size_t)gm * N + gn] = acc[i][j] + bias[gn];
        }
    }
#endif
}

// ============ launch ============
extern "C" void kernel_launch(void* const* d_in, const int* in_sizes, int n_in,
                              void* d_out, int out_size) {
    const float* features = (const float*)d_in[0];
    const int*   captions = (const int*)  d_in[1];
    const int*   lengths  = (const int*)  d_in[2];
    const float* h0       = (const float*)d_in[3];
    const float* c0       = (const float*)d_in[4];
    const float* embed_w  = (const float*)d_in[5];
    const float* w_ih     = (const float*)d_in[6];
    const float* w_hh     = (const float*)d_in[7];
    const float* b_ih     = (const float*)d_in[8];
    const float* b_hh     = (const float*)d_in[9];
    const float* lin_w    = (const float*)d_in[10];
    const float* lin_b    = (const float*)d_in[11];
    float* out = (float*)d_out;
    const int M_total = out_size / VOCAB;

    float *xseq, *xw, *whi, *wlo, *hhi, *hlo, *cstate, *hall, *hc;
    int* off;
    cudaGetSymbolAddress((void**)&xseq,   d_xseq);
    cudaGetSymbolAddress((void**)&xw,     d_xw);
    cudaGetSymbolAddress((void**)&whi,    d_whh_hi);
    cudaGetSymbolAddress((void**)&wlo,    d_whh_lo);
    cudaGetSymbolAddress((void**)&hhi,    d_hhi);
    cudaGetSymbolAddress((void**)&hlo,    d_hlo);
    cudaGetSymbolAddress((void**)&cstate, d_cstate);
    cudaGetSymbolAddress((void**)&hall,   d_hall);
    cudaGetSymbolAddress((void**)&hc,     d_hc);
    cudaGetSymbolAddress((void**)&off,    d_off);

    cudaMemcpyAsync(cstate, c0, BATCH * HDIM * sizeof(float), cudaMemcpyDeviceToDevice, 0);
    split_h0_kernel<<<64, 256>>>(h0, hhi, hlo);
    compute_off_kernel<<<1, 128>>>(lengths, off);
    build_xseq_kernel<<<(TSTEPS * BATCH * EDIM / 4) / 256, 256>>>(features, captions, embed_w, xseq);
    prep_whh_kernel<<<1024, 256>>>(w_hh, whi, wlo);

    // xW = X @ w_ih^T + (b_ih + b_hh)  [2560, 2048] fp32, original gate order
    gemm_nt_kernel<128, 128, 16, 8, 8>
        <<<dim3(GDIM / 128, (TSTEPS * BATCH) / 128), 256>>>(
            xseq, w_ih, b_ih, b_hh, xw, TSTEPS * BATCH, GDIM, EDIM);

    // fused recurrence: one kernel per step, h ping-pong
    const int step_smem = 50176;   // 48K + align pad
    cudaFuncSetAttribute(step_kernel, cudaFuncAttributeMaxDynamicSharedMemorySize, step_smem);
    for (int t = 0; t < TSTEPS; t++) {
        int pi = t & 1, po = (t + 1) & 1;
        step_kernel<<<32, 256, step_smem>>>(
            xw + (size_t)t * BATCH * GDIM,
            hhi + (size_t)pi * BATCH * HDIM, hlo + (size_t)pi * BATCH * HDIM,
            whi, wlo, cstate, hall + (size_t)t * BATCH * HDIM,
            hhi + (size_t)po * BATCH * HDIM, hlo + (size_t)po * BATCH * HDIM);
    }

    gather_h_kernel<<<TSTEPS * BATCH, 128>>>(hall, off, hc);

    const int proj_smem = 68608;
    cudaFuncSetAttribute(proj_tf32_kernel, cudaFuncAttributeMaxDynamicSharedMemorySize, proj_smem);
    proj_tf32_kernel<<<dim3((M_total + 127) / 128, VOCAB / 128), 256, proj_smem>>>(
        hc, lin_w, lin_b, out, M_total, VOCAB, HDIM);
}